// round 1
// baseline (speedup 1.0000x reference)
#include <cuda_runtime.h>
#include <cstdint>

// ---------------------------------------------------------------------------
// NeuralMinSumDecoder — structured Tanner graph:
//   edge e = j*6+l :  var j (r=j%M)  <->  check (A*r+l) mod M,  A=48271
//   A^-1 mod 2^16 = 57967.
//   Check c's 12 edges: l=0..5, vars r_l = A^-1*(c-l) mod M and r_l+M.
//   Variable with base b = A*r mod M touches checks b..b+5 (consecutive!).
// Layout: edge values stored CHECK-major:  idx = c*12 + l*2 + h   (h = j/M)
// ---------------------------------------------------------------------------

#define NV   131072
#define MC   65536
#define DVV  6
#define TMAX 30
#define EDG  (NV * DVV)          // 786432 edges
#define AINV 57967u
#define MMSK 0xFFFFu
#define HOFF (MC * DVV)          // beta offset between h=0 and h=1 halves

__device__ __align__(16) float g_v2c[EDG];
__device__ __align__(16) float g_c2v[EDG];
__device__ __align__(16) float2 g_llr2[MC];   // (llr[r], llr[r+M]) indexed by base b
__device__ int g_synflag[TMAX];               // 0 => syndrome was all-zero at iter t

// ---------------------------------------------------------------------------
// Init: llr pairs by base, v2c = llr[vidx] in check-major layout, reset flags.
// ---------------------------------------------------------------------------
__global__ void k_init(const float* __restrict__ llr) {
    unsigned tid = blockIdx.x * blockDim.x + threadIdx.x;   // 0..MC-1
    // llr pair for base b = tid
    unsigned r = (AINV * tid) & MMSK;
    g_llr2[tid] = make_float2(llr[r], llr[r + MC]);
    // v2c init for check c = tid
    unsigned c = tid;
#pragma unroll
    for (int l = 0; l < DVV; l++) {
        unsigned rl = (AINV * (c - (unsigned)l)) & MMSK;
        g_v2c[c * 12 + l * 2 + 0] = llr[rl];
        g_v2c[c * 12 + l * 2 + 1] = llr[rl + MC];
    }
    if (tid < TMAX) g_synflag[tid] = 0;
}

__device__ __forceinline__ bool frozen_before(int t) {
    int f = 0;
    for (int tt = 0; tt < t; tt++) f |= (g_synflag[tt] == 0);
    return f != 0;
}

// ---------------------------------------------------------------------------
// Check-node update: weighted min-sum with top-2 mins, first-edge-id tiebreak.
// One thread per check. v2c reads / c2v writes fully coalesced (3x float4).
// Beta gathers: beta[e] with e = (r_l + h*M)*6 + l — each variable's 24B beta
// chunk is consumed by 6 consecutive threads -> sector-efficient.
// ---------------------------------------------------------------------------
__global__ void k_check(const float* __restrict__ betas, int t) {
    __shared__ int s_frozen;
    if (threadIdx.x == 0) s_frozen = frozen_before(t);
    __syncthreads();
    if (s_frozen) return;

    unsigned c = blockIdx.x * blockDim.x + threadIdx.x;

    float4 a0 = *(const float4*)&g_v2c[c * 12 + 0];
    float4 a1 = *(const float4*)&g_v2c[c * 12 + 4];
    float4 a2 = *(const float4*)&g_v2c[c * 12 + 8];
    float v[12] = {a0.x, a0.y, a0.z, a0.w, a1.x, a1.y, a1.z, a1.w,
                   a2.x, a2.y, a2.z, a2.w};

    unsigned rl[6];
#pragma unroll
    for (int l = 0; l < 6; l++) rl[l] = (AINV * (c - (unsigned)l)) & MMSK;

    float mag[12];
    int   neg[12];
    int   eid[12];
    int   totneg = 0;
    float m1 = __int_as_float(0x7f800000);   // +inf
    float m2 = m1;
    int   e1 = 0x7fffffff;

#pragma unroll
    for (int l = 0; l < 6; l++) {
#pragma unroll
        for (int h = 0; h < 2; h++) {
            int i = l * 2 + h;
            int e = (int)((rl[l] + (unsigned)h * MC) * 6u + (unsigned)l);
            eid[i] = e;
            float m = fabsf(v[i]);
            mag[i]  = m;
            int  n  = (v[i] < 0.0f) ? 1 : 0;
            neg[i]  = n;
            totneg += n;
            if (m < m1)      { m2 = m1; m1 = m; e1 = e; }
            else if (m == m1){ m2 = m1; if (e < e1) e1 = e; }
            else if (m < m2) { m2 = m; }
        }
    }

    const float* bt = betas + (size_t)t * EDG;
    float o[12];
#pragma unroll
    for (int l = 0; l < 6; l++) {
#pragma unroll
        for (int h = 0; h < 2; h++) {
            int i = l * 2 + h;
            float beta = bt[rl[l] * 6u + (unsigned)l + (unsigned)h * HOFF];
            float sel  = (eid[i] == e1) ? m2 : m1;
            float val  = beta * sel;
            o[i] = ((totneg - neg[i]) & 1) ? -val : val;
        }
    }

    *(float4*)&g_c2v[c * 12 + 0] = make_float4(o[0], o[1], o[2],  o[3]);
    *(float4*)&g_c2v[c * 12 + 4] = make_float4(o[4], o[5], o[6],  o[7]);
    *(float4*)&g_c2v[c * 12 + 8] = make_float4(o[8], o[9], o[10], o[11]);
}

// ---------------------------------------------------------------------------
// Variable-node update + in-block syndrome.
// One thread per base b (handles both halves j=r, j=r+M as a float2 lane).
// Reads/writes the banded window checks b..b+5. Syndrome of check c = XOR of
// bits over bases c-5..c  -> computed via smem with a 5-base halo.
// ---------------------------------------------------------------------------
__global__ void k_var(int t) {
    __shared__ int s_frozen;
    __shared__ unsigned char sp[256 + 5];
    if (threadIdx.x == 0) s_frozen = frozen_before(t);
    __syncthreads();
    if (s_frozen) return;

    unsigned b0  = blockIdx.x * 256u;
    unsigned tid = threadIdx.x;
    unsigned b   = b0 + tid;

    float2 cv[6];
    float s0 = 0.0f, s1 = 0.0f;
#pragma unroll
    for (int l = 0; l < 6; l++) {
        unsigned c = (b + (unsigned)l) & MMSK;
        cv[l] = *(const float2*)&g_c2v[c * 12 + l * 2];
        s0 += cv[l].x; s1 += cv[l].y;
    }
    float2 L  = g_llr2[b];
    float  t0 = L.x + s0;
    float  t1 = L.y + s1;
#pragma unroll
    for (int l = 0; l < 6; l++) {
        unsigned c = (b + (unsigned)l) & MMSK;
        *(float2*)&g_v2c[c * 12 + l * 2] = make_float2(t0 - cv[l].x, t1 - cv[l].y);
    }
    sp[tid + 5] = (unsigned char)(((t0 < 0.0f) ? 1 : 0) ^ ((t1 < 0.0f) ? 1 : 0));

    if (tid < 5) {   // halo bases b0-5..b0-1 (bit-only, recomputed redundantly)
        unsigned bh = (b0 - 5u + tid) & MMSK;
        float h0 = 0.0f, h1 = 0.0f;
#pragma unroll
        for (int l = 0; l < 6; l++) {
            unsigned c = (bh + (unsigned)l) & MMSK;
            float2 x = *(const float2*)&g_c2v[c * 12 + l * 2];
            h0 += x.x; h1 += x.y;
        }
        float2 Lh = g_llr2[bh];
        sp[tid] = (unsigned char)((((Lh.x + h0) < 0.0f) ? 1 : 0) ^
                                  (((Lh.y + h1) < 0.0f) ? 1 : 0));
    }
    __syncthreads();

    // syndrome of check c = b0 + tid
    int par = sp[tid] ^ sp[tid + 1] ^ sp[tid + 2] ^ sp[tid + 3] ^ sp[tid + 4] ^
              sp[tid + 5];
    int anyodd = __syncthreads_or(par);
    if (anyodd && tid == 0) g_synflag[t] = 1;   // benign same-value race
}

// ---------------------------------------------------------------------------
// Output: posterior = llr + sum(c2v), decoded = posterior < 0, iters.
// d_out (float32): [0,N) decoded, [N,2N) posterior, [2N] iters.
// ---------------------------------------------------------------------------
__global__ void k_out(float* __restrict__ out, int out_size) {
    unsigned b = blockIdx.x * blockDim.x + threadIdx.x;   // base, 0..MC-1
    float s0 = 0.0f, s1 = 0.0f;
#pragma unroll
    for (int l = 0; l < 6; l++) {
        unsigned c = (b + (unsigned)l) & MMSK;
        float2 x = *(const float2*)&g_c2v[c * 12 + l * 2];
        s0 += x.x; s1 += x.y;
    }
    float2 L  = g_llr2[b];
    float  p0 = L.x + s0;
    float  p1 = L.y + s1;
    unsigned r = (AINV * b) & MMSK;

    if ((int)r < out_size)            out[r]            = (p0 < 0.0f) ? 1.0f : 0.0f;
    if ((int)(r + MC) < out_size)     out[r + MC]       = (p1 < 0.0f) ? 1.0f : 0.0f;
    if ((int)(NV + r) < out_size)     out[NV + r]       = p0;
    if ((int)(NV + r + MC) < out_size)out[NV + r + MC]  = p1;

    if (b == 0 && 2 * NV < out_size) {
        int iters = TMAX;
        for (int tt = 0; tt < TMAX; tt++)
            if (g_synflag[tt] == 0) { iters = tt + 1; break; }
        out[2 * NV] = (float)iters;
    }
}

// ---------------------------------------------------------------------------
extern "C" void kernel_launch(void* const* d_in, const int* in_sizes, int n_in,
                              void* d_out, int out_size) {
    const float* llr   = (const float*)d_in[0];
    const float* betas = (const float*)d_in[1];
    (void)in_sizes; (void)n_in;

    dim3 blk(256), grd(MC / 256);
    k_init<<<grd, blk>>>(llr);
    for (int t = 0; t < TMAX; t++) {
        k_check<<<grd, blk>>>(betas, t);
        k_var<<<grd, blk>>>(t);
    }
    k_out<<<grd, blk>>>((float*)d_out, out_size);
}

// round 2
// speedup vs baseline: 1.2097x; 1.2097x over previous
#include <cuda_runtime.h>
#include <cstdint>

// ---------------------------------------------------------------------------
// NeuralMinSumDecoder — structured Tanner graph, fused check+var per iteration.
//   edge e = j*6+l :  var j (r=j%M)  <->  check (A*r+l) mod M,  A=48271
//   A^-1 mod 2^16 = 57967.  Variable base b = A*r mod M touches checks b..b+5.
// v2c stored CHECK-major: idx = c*12 + l*2 + h  (h = j/M).
// c2v lives only in shared memory (10-check halo per block).
// ---------------------------------------------------------------------------

#define NV   131072
#define MC   65536
#define DVV  6
#define TMAX 30
#define EDG  (NV * DVV)
#define AINV 57967u
#define MMSK 0xFFFFu
#define HOFF (MC * DVV)
#define NB   128                 // bases (and checks) per block
#define GRD  (MC / NB)           // 512 blocks
#define NCHK (NB + 10)           // checks computed per block (5 halo each side)

__device__ __align__(16) float  g_v2c[EDG];
__device__ __align__(16) float2 g_llr2[MC];    // (llr[r], llr[r+M]) by base b
__device__ __align__(16) float2 g_post2[MC];   // posterior pair by base b
__device__ int g_synflag[TMAX];                // 0 => syndrome all-zero at iter t

// ---------------------------------------------------------------------------
__global__ void k_init(const float* __restrict__ llr) {
    unsigned tid = blockIdx.x * blockDim.x + threadIdx.x;   // 0..MC-1
    unsigned r = (AINV * tid) & MMSK;
    g_llr2[tid] = make_float2(llr[r], llr[r + MC]);
    unsigned c = tid;
#pragma unroll
    for (int l = 0; l < DVV; l++) {
        unsigned rl = (AINV * (c - (unsigned)l)) & MMSK;
        g_v2c[c * 12 + l * 2 + 0] = llr[rl];
        g_v2c[c * 12 + l * 2 + 1] = llr[rl + MC];
    }
    if (tid < TMAX) g_synflag[tid] = 0;
}

// ---------------------------------------------------------------------------
// One fused iteration: check update (smem c2v, with halo) + variable update +
// posterior + in-block syndrome.
// ---------------------------------------------------------------------------
__global__ __launch_bounds__(NB) void k_fused(const float* __restrict__ betas,
                                              int t) {
    __shared__ float s_c2v[NCHK][13];          // 13-word stride: conflict-free
    __shared__ unsigned char sp[NB + 5];
    __shared__ int s_frozen;

    int tid = threadIdx.x;
    if (tid == 0) {
        int f = 0;
        for (int tt = 0; tt < t; tt++) f |= (g_synflag[tt] == 0);
        s_frozen = f;
    }
    __syncthreads();
    if (s_frozen) return;

    unsigned B0 = blockIdx.x * NB;
    const float* bt = betas + (size_t)t * EDG;

    // ---- check phase: checks (B0-5 .. B0+NB+4) mod M ----
    for (int k = tid; k < NCHK; k += NB) {
        unsigned c = (B0 - 5u + (unsigned)k) & MMSK;

        float4 a0 = *(const float4*)&g_v2c[c * 12 + 0];
        float4 a1 = *(const float4*)&g_v2c[c * 12 + 4];
        float4 a2 = *(const float4*)&g_v2c[c * 12 + 8];
        float v[12] = {a0.x, a0.y, a0.z, a0.w, a1.x, a1.y, a1.z, a1.w,
                       a2.x, a2.y, a2.z, a2.w};

        unsigned rl[6];
#pragma unroll
        for (int l = 0; l < 6; l++) rl[l] = (AINV * (c - (unsigned)l)) & MMSK;

        float beta[12];
#pragma unroll
        for (int l = 0; l < 6; l++) {
            beta[l * 2 + 0] = bt[rl[l] * 6u + (unsigned)l];
            beta[l * 2 + 1] = bt[rl[l] * 6u + (unsigned)l + HOFF];
        }

        int   neg[12];
        int   eid[12];
        int   totneg = 0;
        float m1 = __int_as_float(0x7f800000);
        float m2 = m1;
        int   e1 = 0x7fffffff;
#pragma unroll
        for (int l = 0; l < 6; l++) {
#pragma unroll
            for (int h = 0; h < 2; h++) {
                int i = l * 2 + h;
                int e = (int)((rl[l] + (unsigned)h * MC) * 6u + (unsigned)l);
                eid[i] = e;
                float m = fabsf(v[i]);
                int  n  = (v[i] < 0.0f) ? 1 : 0;
                neg[i]  = n;
                totneg += n;
                if (m < m1)       { m2 = m1; m1 = m; e1 = e; }
                else if (m == m1) { m2 = m1; if (e < e1) e1 = e; }
                else if (m < m2)  { m2 = m; }
            }
        }
#pragma unroll
        for (int i = 0; i < 12; i++) {
            float sel = (eid[i] == e1) ? m2 : m1;
            float val = beta[i] * sel;
            s_c2v[k][i] = ((totneg - neg[i]) & 1) ? -val : val;
        }
    }
    __syncthreads();

    // ---- variable phase: base b = B0 + tid ----
    unsigned b = (B0 + (unsigned)tid) & MMSK;
    float cv0[6], cv1[6];
    float s0 = 0.0f, s1 = 0.0f;
#pragma unroll
    for (int l = 0; l < 6; l++) {
        cv0[l] = s_c2v[5 + tid + l][l * 2 + 0];
        cv1[l] = s_c2v[5 + tid + l][l * 2 + 1];
        s0 += cv0[l]; s1 += cv1[l];
    }
    float2 L  = g_llr2[b];
    float  t0 = L.x + s0;
    float  t1 = L.y + s1;
#pragma unroll
    for (int l = 0; l < 6; l++) {
        unsigned c = (b + (unsigned)l) & MMSK;
        *(float2*)&g_v2c[c * 12 + l * 2] = make_float2(t0 - cv0[l], t1 - cv1[l]);
    }
    g_post2[b] = make_float2(t0, t1);
    sp[tid + 5] = (unsigned char)(((t0 < 0.0f) ? 1 : 0) ^
                                  ((t1 < 0.0f) ? 1 : 0));

    if (tid < 5) {   // halo bases B0-5..B0-1 (bit only, from smem halo checks)
        unsigned bh = (B0 - 5u + (unsigned)tid) & MMSK;
        float h0 = 0.0f, h1 = 0.0f;
#pragma unroll
        for (int l = 0; l < 6; l++) {
            h0 += s_c2v[tid + l][l * 2 + 0];
            h1 += s_c2v[tid + l][l * 2 + 1];
        }
        float2 Lh = g_llr2[bh];
        sp[tid] = (unsigned char)((((Lh.x + h0) < 0.0f) ? 1 : 0) ^
                                  (((Lh.y + h1) < 0.0f) ? 1 : 0));
    }
    __syncthreads();

    // ---- syndrome of checks B0..B0+NB-1 ----
    int par = sp[tid] ^ sp[tid + 1] ^ sp[tid + 2] ^ sp[tid + 3] ^ sp[tid + 4] ^
              sp[tid + 5];
    int anyodd = __syncthreads_or(par);
    if (anyodd && tid == 0) g_synflag[t] = 1;   // benign same-value race
}

// ---------------------------------------------------------------------------
// Output from stored posterior: [0,N) decoded, [N,2N) posterior, [2N] iters.
// ---------------------------------------------------------------------------
__global__ void k_out(float* __restrict__ out, int out_size) {
    unsigned b = blockIdx.x * blockDim.x + threadIdx.x;   // base 0..MC-1
    float2 P = g_post2[b];
    unsigned r = (AINV * b) & MMSK;

    if ((int)r < out_size)             out[r]           = (P.x < 0.0f) ? 1.0f : 0.0f;
    if ((int)(r + MC) < out_size)      out[r + MC]      = (P.y < 0.0f) ? 1.0f : 0.0f;
    if ((int)(NV + r) < out_size)      out[NV + r]      = P.x;
    if ((int)(NV + r + MC) < out_size) out[NV + r + MC] = P.y;

    if (b == 0 && 2 * NV < out_size) {
        int iters = TMAX;
        for (int tt = 0; tt < TMAX; tt++)
            if (g_synflag[tt] == 0) { iters = tt + 1; break; }
        out[2 * NV] = (float)iters;
    }
}

// ---------------------------------------------------------------------------
extern "C" void kernel_launch(void* const* d_in, const int* in_sizes, int n_in,
                              void* d_out, int out_size) {
    const float* llr   = (const float*)d_in[0];
    const float* betas = (const float*)d_in[1];
    (void)in_sizes; (void)n_in;

    k_init<<<GRD, NB>>>(llr);
    for (int t = 0; t < TMAX; t++)
        k_fused<<<GRD, NB>>>(betas, t);
    k_out<<<GRD, NB>>>((float*)d_out, out_size);
}

// round 3
// speedup vs baseline: 1.2395x; 1.0246x over previous
#include <cuda_runtime.h>
#include <cstdint>

// ---------------------------------------------------------------------------
// NeuralMinSumDecoder — banded Tanner graph, K iterations fused per launch.
//   A=48271, A^-1 mod 2^16 = 57967. Base b = A*r mod M touches checks b..b+5;
//   check c touches bases c-5..c (each with two halves h=0/1 -> 12 edges).
// Trapezoid: valid base interval shrinks by 5 per side per iteration, so a
// block owning NB bases loads v2c for W = NB + 10K + 5 check-slots, runs K
// full iterations entirely in shared memory, then writes back owned entries.
// Thread mapping: 2 threads per slot (one per half h), merged via shfl_xor.
// ---------------------------------------------------------------------------

#define MCC   65536
#define NVV   131072
#define TMAXX 30
#define EDG   (NVV * 6)
#define AINV  57967u
#define MMSK  0xFFFFu
#define HOFF  (MCC * 6)

#define NB    128                 // owned bases per block
#define KK    3                   // iterations per launch
#define HL    (5 * KK + 5)        // 20 (extra 5 for syndrome halo)
#define HR    (5 * KK)            // 15
#define WW    (NB + HL + HR)      // 163 slots
#define THR   (2 * NB)            // 256 threads
#define GRD   (MCC / NB)          // 512 blocks
#define NLAUNCH (TMAXX / KK)      // 10

__device__ __align__(16) float g_v2c[EDG];     // c*12 + l*2 + h
__device__ float g_llrh[2 * MCC];              // llr half, idx b*2+h
__device__ float g_post[2 * MCC];              // posterior half, idx b*2+h
__device__ int   g_synflag[TMAXX];             // 0 => syndrome all-zero at t

// ---------------------------------------------------------------------------
__global__ void k_init(const float* __restrict__ llr) {
    unsigned tid = blockIdx.x * blockDim.x + threadIdx.x;   // 0..MC-1
    unsigned r = (AINV * tid) & MMSK;
    g_llrh[2 * tid + 0] = llr[r];
    g_llrh[2 * tid + 1] = llr[r + MCC];
    unsigned c = tid;
#pragma unroll
    for (int l = 0; l < 6; l++) {
        unsigned rl = (AINV * (c - (unsigned)l)) & MMSK;
        g_v2c[c * 12 + l * 2 + 0] = llr[rl];
        g_v2c[c * 12 + l * 2 + 1] = llr[rl + MCC];
    }
    if (tid < TMAXX) g_synflag[tid] = 0;
}

// ---------------------------------------------------------------------------
__global__ __launch_bounds__(THR) void k_fused(const float* __restrict__ betas,
                                               int t0) {
    __shared__ float s_v2c[WW * 13];       // stride 13: conflict-free
    __shared__ float s_c2v[WW * 13];
    __shared__ float s_llr[WW * 2];
    __shared__ unsigned char sp[NB + 6];
    __shared__ int s_frozen;

    int tid = threadIdx.x;
    int h   = tid & 1;
    int sl0 = tid >> 1;
    unsigned B0 = blockIdx.x * NB;

    if (tid == 0) {
        int f = 0;
        for (int tt = 0; tt < t0; tt++) f |= (g_synflag[tt] == 0);
        s_frozen = f;
    }
    __syncthreads();
    if (s_frozen) return;

    // ---- load v2c region + llr halves into smem ----
    for (int i = tid; i < WW; i += THR) {
        unsigned c = (B0 - (unsigned)HL + (unsigned)i) & MMSK;
        const float4* src = (const float4*)&g_v2c[c * 12];
        float4 x = src[0], y = src[1], z = src[2];
        float* row = &s_v2c[i * 13];
        row[0] = x.x; row[1] = x.y; row[2]  = x.z; row[3]  = x.w;
        row[4] = y.x; row[5] = y.y; row[6]  = y.z; row[7]  = y.w;
        row[8] = z.x; row[9] = z.y; row[10] = z.z; row[11] = z.w;
        s_llr[i * 2 + 0] = g_llrh[c * 2 + 0];
        s_llr[i * 2 + 1] = g_llrh[c * 2 + 1];
    }
    __syncthreads();

    for (int k = 1; k <= KK; k++) {
        const float* bt = betas + (size_t)(t0 + k - 1) * EDG;

        // ---- check phase: slots [5k, WW - 5(k-1)) ----
        int clo = 5 * k, chi = WW - 5 * (k - 1);
        for (int sb = clo; sb < chi; sb += NB) {
            int  s   = sb + sl0;
            bool act = s < chi;
            int  sc  = act ? s : clo;
            unsigned c = (B0 - (unsigned)HL + (unsigned)sc) & MMSK;

            float v[6], beta[6];
            int   eid6[6], neg6[6], negc = 0;
            float m1 = __int_as_float(0x7f800000), m2 = m1;
            int   e1 = 0x7fffffff;
#pragma unroll
            for (int l = 0; l < 6; l++) {
                unsigned rl = (AINV * (c - (unsigned)l)) & MMSK;
                v[l]    = s_v2c[sc * 13 + l * 2 + h];
                beta[l] = act ? bt[rl * 6u + (unsigned)l + (unsigned)h * HOFF]
                              : 0.0f;
                eid6[l] = (int)((rl + (unsigned)h * MCC) * 6u + (unsigned)l);
                float m = fabsf(v[l]);
                int   n = (v[l] < 0.0f) ? 1 : 0;
                neg6[l] = n; negc += n;
                if (m < m1)       { m2 = m1; m1 = m; e1 = eid6[l]; }
                else if (m == m1) { m2 = m1; if (eid6[l] < e1) e1 = eid6[l]; }
                else if (m < m2)  { m2 = m; }
            }
            // merge the two halves (partner lane = lane^1)
            float om1 = __shfl_xor_sync(0xffffffffu, m1, 1);
            float om2 = __shfl_xor_sync(0xffffffffu, m2, 1);
            int   oe1 = __shfl_xor_sync(0xffffffffu, e1, 1);
            int   onc = __shfl_xor_sync(0xffffffffu, negc, 1);
            float M1, M2; int E1;
            if (m1 == om1)     { M1 = m1;  M2 = m1;             E1 = min(e1, oe1); }
            else if (m1 < om1) { M1 = m1;  M2 = fminf(m2, om1); E1 = e1; }
            else               { M1 = om1; M2 = fminf(om2, m1); E1 = oe1; }
            int tot = negc + onc;

            if (act) {
#pragma unroll
                for (int l = 0; l < 6; l++) {
                    float sel = (eid6[l] == E1) ? M2 : M1;
                    float val = beta[l] * sel;
                    s_c2v[s * 13 + l * 2 + h] =
                        ((tot - neg6[l]) & 1) ? -val : val;
                }
            }
        }
        __syncthreads();

        // ---- variable phase: slots [5k, WW - 5k) ----
        int vlo = 5 * k, vhi = WW - 5 * k;
        for (int sb = vlo; sb < vhi; sb += NB) {
            int  s   = sb + sl0;
            bool act = s < vhi;
            int  sc  = act ? s : vlo;

            float cv[6], sum = 0.0f;
#pragma unroll
            for (int l = 0; l < 6; l++) {
                cv[l] = s_c2v[(sc + l) * 13 + l * 2 + h];
                sum  += cv[l];
            }
            float tp = s_llr[sc * 2 + h] + sum;

            if (k < KK) {
                if (act) {
#pragma unroll
                    for (int l = 0; l < 6; l++)
                        s_v2c[(s + l) * 13 + l * 2 + h] = tp - cv[l];
                }
            } else {                                  // last step: write global
                if (act && s >= HL && s < HL + NB) {
                    unsigned b = (B0 - (unsigned)HL + (unsigned)s) & MMSK;
#pragma unroll
                    for (int l = 0; l < 6; l++)
                        g_v2c[((b + (unsigned)l) & MMSK) * 12 + l * 2 + h] =
                            tp - cv[l];
                    g_post[b * 2 + (unsigned)h] = tp;
                }
            }
            int bit = (tp < 0.0f) ? 1 : 0;
            bit ^= __shfl_xor_sync(0xffffffffu, bit, 1);
            if (act && h == 0 && s >= HL - 5 && s < HL + NB)
                sp[s - (HL - 5)] = (unsigned char)bit;
        }
        __syncthreads();

        // ---- syndrome of owned checks B0..B0+NB-1 at iteration t0+k-1 ----
        int par = 0;
        if (tid < NB)
            par = sp[tid] ^ sp[tid + 1] ^ sp[tid + 2] ^ sp[tid + 3] ^
                  sp[tid + 4] ^ sp[tid + 5];
        int anyodd = __syncthreads_or(par);
        if (anyodd && tid == 0) g_synflag[t0 + k - 1] = 1;  // benign race
    }
}

// ---------------------------------------------------------------------------
__global__ void k_out(float* __restrict__ out, int out_size) {
    unsigned b = blockIdx.x * blockDim.x + threadIdx.x;   // base 0..MC-1
    float p0 = g_post[b * 2 + 0];
    float p1 = g_post[b * 2 + 1];
    unsigned r = (AINV * b) & MMSK;

    if ((int)r < out_size)              out[r]            = (p0 < 0.0f) ? 1.0f : 0.0f;
    if ((int)(r + MCC) < out_size)      out[r + MCC]      = (p1 < 0.0f) ? 1.0f : 0.0f;
    if ((int)(NVV + r) < out_size)      out[NVV + r]      = p0;
    if ((int)(NVV + r + MCC) < out_size)out[NVV + r + MCC]= p1;

    if (b == 0 && 2 * NVV < out_size) {
        int iters = TMAXX;
        for (int tt = 0; tt < TMAXX; tt++)
            if (g_synflag[tt] == 0) { iters = tt + 1; break; }
        out[2 * NVV] = (float)iters;
    }
}

// ---------------------------------------------------------------------------
extern "C" void kernel_launch(void* const* d_in, const int* in_sizes, int n_in,
                              void* d_out, int out_size) {
    const float* llr   = (const float*)d_in[0];
    const float* betas = (const float*)d_in[1];
    (void)in_sizes; (void)n_in;

    k_init<<<MCC / 256, 256>>>(llr);
    for (int g = 0; g < NLAUNCH; g++)
        k_fused<<<GRD, THR>>>(betas, g * KK);
    k_out<<<MCC / 256, 256>>>((float*)d_out, out_size);
}

// round 4
// speedup vs baseline: 1.8448x; 1.4883x over previous
#include <cuda_runtime.h>
#include <cstdint>

// ---------------------------------------------------------------------------
// NeuralMinSumDecoder — banded Tanner graph (A=48271, A^-1=57967 mod 2^16).
// Base b touches checks b..b+5; check c touches bases c-5..c, halves h=0/1.
// KK iterations fused per launch; full-width compute (garbage confined to
// halo), fixed slot per thread, h-plane smem (stride PL=1008 -> conflict-free
// float2), double-buffered global v2c.
// ---------------------------------------------------------------------------

#define MCC   65536
#define NVV   131072
#define TMAXX 30
#define EDG   (NVV * 6)
#define MC6   (MCC * 6)
#define AINV  57967u
#define MMSK  0xFFFFu
#define HOFF  MC6

#define NB    128                 // owned bases/checks per block
#define KK    3                   // iterations per launch
#define HL    20                  // left halo (5*KK + 5 for syndrome)
#define HR    15                  // right halo (5*KK)
#define WW    (NB + HL + HR)      // 163 slots
#define THR   352                 // >= 2*WW = 326, warp multiple
#define GRD   (MCC / NB)          // 512 blocks
#define NLAUNCH (TMAXX / KK)      // 10
#define PL    1008                // h-plane stride: even, ==16 mod 32, >=978

__device__ __align__(16) float g_v2c[2][2 * MC6]; // [buf][h*MC6 + c*6 + l]
__device__ float g_llrh[2 * MCC];                 // [h*MC + b]
__device__ float g_post[2 * MCC];                 // [h*MC + b]
__device__ int   g_synflag[TMAXX];                // 0 => syndrome all-zero at t

// ---------------------------------------------------------------------------
__global__ void k_init(const float* __restrict__ llr) {
    unsigned c = blockIdx.x * blockDim.x + threadIdx.x;   // 0..MC-1
    unsigned r = (AINV * c) & MMSK;
    g_llrh[c]       = llr[r];
    g_llrh[MCC + c] = llr[r + MCC];
#pragma unroll
    for (int l = 0; l < 6; l++) {
        unsigned rl = (AINV * (c - (unsigned)l)) & MMSK;
        g_v2c[0][c * 6 + l]       = llr[rl];
        g_v2c[0][MC6 + c * 6 + l] = llr[rl + MCC];
    }
    if (c < TMAXX) g_synflag[c] = 0;
}

// ---------------------------------------------------------------------------
__global__ __launch_bounds__(THR, 4) void k_fused(
        const float* __restrict__ betas, int t0, int rbuf) {
    __shared__ float s_v2c[2 * PL];
    __shared__ float s_c2v[2 * PL];
    __shared__ unsigned char sp[NB + 5];
    __shared__ int s_frozen;

    int tid = threadIdx.x;
    if (tid == 0) {
        int f = 0;
        for (int tt = 0; tt < t0; tt++) f |= (g_synflag[tt] == 0);
        s_frozen = f;
    }
    __syncthreads();
    if (s_frozen) return;

    int  h    = tid & 1;
    int  sl   = tid >> 1;
    bool act  = sl < WW;
    int  s    = act ? sl : WW - 1;      // clamped slot for loads
    bool actv = sl < WW - 5;
    int  sv   = actv ? sl : 0;          // clamped slot for var-phase reads
    unsigned B0 = blockIdx.x * NB;
    unsigned c  = (B0 - (unsigned)HL + (unsigned)s) & MMSK;

    // loop-invariant per-slot constants
    int off[6];                          // beta offset == edge id
#pragma unroll
    for (int l = 0; l < 6; l++) {
        unsigned rl = (AINV * (c - (unsigned)l)) & MMSK;
        off[l] = (int)(rl * 6u + (unsigned)l) + h * HOFF;
    }
    float llr = g_llrh[h * MCC + (int)c];

    float* v2 = s_v2c + h * PL;
    float* c2 = s_c2v + h * PL;

    // load v2c region (h-plane, vectorized, coalesced)
    const float* gsrc = g_v2c[rbuf] + h * MC6 + (int)c * 6;
    float2 L0 = *(const float2*)(gsrc + 0);
    float2 L1 = *(const float2*)(gsrc + 2);
    float2 L2 = *(const float2*)(gsrc + 4);
    if (act) {
        *(float2*)(v2 + s * 6 + 0) = L0;
        *(float2*)(v2 + s * 6 + 2) = L1;
        *(float2*)(v2 + s * 6 + 4) = L2;
    }
    float* gdst = g_v2c[rbuf ^ 1] + h * MC6;
    __syncthreads();

    for (int k = 1; k <= KK; k++) {
        const float* bt = betas + (size_t)(t0 + k - 1) * EDG;

        // ---- check phase (all slots; halo garbage is confined) ----
        float2 a0 = *(const float2*)(v2 + s * 6 + 0);
        float2 a1 = *(const float2*)(v2 + s * 6 + 2);
        float2 a2 = *(const float2*)(v2 + s * 6 + 4);
        float v[6] = {a0.x, a0.y, a1.x, a1.y, a2.x, a2.y};
        float beta[6];
#pragma unroll
        for (int l = 0; l < 6; l++) beta[l] = bt[off[l]];

        int   neg6[6], negc = 0;
        float m1 = __int_as_float(0x7f800000), m2 = m1;
        int   e1 = 0x7fffffff;
#pragma unroll
        for (int l = 0; l < 6; l++) {
            float m = fabsf(v[l]);
            int   n = (v[l] < 0.0f) ? 1 : 0;
            neg6[l] = n; negc += n;
            if (m < m1)       { m2 = m1; m1 = m; e1 = off[l]; }
            else if (m == m1) { m2 = m1; if (off[l] < e1) e1 = off[l]; }
            else if (m < m2)  { m2 = m; }
        }
        // merge halves (partner = lane^1; pairs always converged)
        float om1 = __shfl_xor_sync(0xffffffffu, m1, 1);
        float om2 = __shfl_xor_sync(0xffffffffu, m2, 1);
        int   oe1 = __shfl_xor_sync(0xffffffffu, e1, 1);
        int   onc = __shfl_xor_sync(0xffffffffu, negc, 1);
        float M1, M2; int E1;
        if (m1 == om1)     { M1 = m1;  M2 = m1;             E1 = min(e1, oe1); }
        else if (m1 < om1) { M1 = m1;  M2 = fminf(m2, om1); E1 = e1; }
        else               { M1 = om1; M2 = fminf(om2, m1); E1 = oe1; }
        int tot = negc + onc;

        float o[6];
#pragma unroll
        for (int l = 0; l < 6; l++) {
            float sel = (off[l] == E1) ? M2 : M1;
            float val = beta[l] * sel;
            o[l] = ((tot - neg6[l]) & 1) ? -val : val;
        }
        if (act) {
            *(float2*)(c2 + s * 6 + 0) = make_float2(o[0], o[1]);
            *(float2*)(c2 + s * 6 + 2) = make_float2(o[2], o[3]);
            *(float2*)(c2 + s * 6 + 4) = make_float2(o[4], o[5]);
        }
        __syncthreads();

        // ---- variable phase ----
        float cv[6], sum = 0.0f;
#pragma unroll
        for (int l = 0; l < 6; l++) {
            cv[l] = c2[(sv + l) * 6 + l];
            sum  += cv[l];
        }
        float tp = llr + sum;

        if (k < KK) {
            if (actv) {
#pragma unroll
                for (int l = 0; l < 6; l++)
                    v2[(sv + l) * 6 + l] = tp - cv[l];
            }
        } else if (sl >= HL && sl < HL + NB) {        // owned writeback
            unsigned b = c;                            // s == sl here
#pragma unroll
            for (int l = 0; l < 6; l++)
                gdst[(int)(((b + (unsigned)l) & MMSK) * 6u + (unsigned)l)] =
                    tp - cv[l];
            g_post[h * MCC + (int)b] = tp;
        }

        int bit = (tp < 0.0f) ? 1 : 0;
        bit ^= __shfl_xor_sync(0xffffffffu, bit, 1);
        if (h == 0 && sl >= HL - 5 && sl < HL + NB)
            sp[sl - (HL - 5)] = (unsigned char)bit;
        __syncthreads();

        int par = 0;
        if (tid < NB)
            par = sp[tid] ^ sp[tid + 1] ^ sp[tid + 2] ^ sp[tid + 3] ^
                  sp[tid + 4] ^ sp[tid + 5];
        int anyodd = __syncthreads_or(par);
        if (anyodd && tid == 0) g_synflag[t0 + k - 1] = 1;   // benign race
    }
}

// ---------------------------------------------------------------------------
__global__ void k_out(float* __restrict__ out, int out_size) {
    unsigned b = blockIdx.x * blockDim.x + threadIdx.x;   // base 0..MC-1
    float p0 = g_post[b];
    float p1 = g_post[MCC + b];
    unsigned r = (AINV * b) & MMSK;

    if ((int)r < out_size)               out[r]             = (p0 < 0.0f) ? 1.0f : 0.0f;
    if ((int)(r + MCC) < out_size)       out[r + MCC]       = (p1 < 0.0f) ? 1.0f : 0.0f;
    if ((int)(NVV + r) < out_size)       out[NVV + r]       = p0;
    if ((int)(NVV + r + MCC) < out_size) out[NVV + r + MCC] = p1;

    if (b == 0 && 2 * NVV < out_size) {
        int iters = TMAXX;
        for (int tt = 0; tt < TMAXX; tt++)
            if (g_synflag[tt] == 0) { iters = tt + 1; break; }
        out[2 * NVV] = (float)iters;
    }
}

// ---------------------------------------------------------------------------
extern "C" void kernel_launch(void* const* d_in, const int* in_sizes, int n_in,
                              void* d_out, int out_size) {
    const float* llr   = (const float*)d_in[0];
    const float* betas = (const float*)d_in[1];
    (void)in_sizes; (void)n_in;

    k_init<<<MCC / 256, 256>>>(llr);
    for (int g = 0; g < NLAUNCH; g++)
        k_fused<<<GRD, THR>>>(betas, g * KK, g & 1);
    k_out<<<MCC / 256, 256>>>((float*)d_out, out_size);
}

// round 7
// speedup vs baseline: 2.3484x; 1.2730x over previous
#include <cuda_runtime.h>
#include <cstdint>

// ---------------------------------------------------------------------------
// NeuralMinSumDecoder — banded Tanner graph (A=48271, A^-1=57967 mod 2^16).
// Base b touches checks b..b+5; check c touches bases c-5..c, halves h=0/1.
// One thread per slot handling BOTH halves as float2. KK iterations fused per
// launch; betas staged through smem with software prefetch; single in-place
// smem message array (stride 13 float2 -> all accesses bank-conflict-free).
// ---------------------------------------------------------------------------

#define MCC   65536
#define NVV   131072
#define TMAXX 30
#define EDG   (NVV * 6)
#define MC6   (MCC * 6)
#define AINV  57967u
#define MMSK  0xFFFFu

#define NB    128                 // owned bases/checks per block
#define KK    3                   // iterations per launch
#define HL    20                  // left halo (5*KK + 5 for syndrome)
#define HR    15                  // right halo (5*KK)
#define WW    (NB + HL + HR)      // 163 slots
#define THR   192                 // one thread per slot (warp multiple)
#define GRD   (MCC / NB)          // 512 blocks
#define NLAUNCH (TMAXX / KK)      // 10
#define ST    13                  // smem row stride in float2 (conflict-free)

__device__ __align__(16) float2 g_v2c[2][MC6];  // [buf][c*6+l] = (h0,h1)
__device__ float2 g_llr2[MCC];                  // (llr[r], llr[r+M]) by base b
__device__ float2 g_post[MCC];                  // posterior pair by base b
__device__ int    g_synflag[TMAXX];             // 0 => syndrome all-zero at t

// ---------------------------------------------------------------------------
__global__ void k_init(const float* __restrict__ llr) {
    unsigned c = blockIdx.x * blockDim.x + threadIdx.x;   // 0..MC-1
    unsigned r = (AINV * c) & MMSK;
    g_llr2[c] = make_float2(llr[r], llr[r + MCC]);
#pragma unroll
    for (int l = 0; l < 6; l++) {
        unsigned rl = (AINV * (c - (unsigned)l)) & MMSK;
        g_v2c[0][c * 6 + l] = make_float2(llr[rl], llr[rl + MCC]);
    }
    if (c < TMAXX) g_synflag[c] = 0;
}

// ---------------------------------------------------------------------------
__global__ __launch_bounds__(THR, 4) void k_fused(
        const float* __restrict__ betas, int t0, int rbuf) {
    __shared__ float2 s_msg[WW * ST];            // v2c / c2v, in place
    __shared__ float2 s_beta[(WW + 5) * ST];     // 5-row front pad
    __shared__ unsigned char sp[NB + 6];
    __shared__ int s_frozen;

    int tid = threadIdx.x;
    if (tid == 0) {
        int f = 0;
        for (int tt = 0; tt < t0; tt++) f |= (g_synflag[tt] == 0);
        s_frozen = f;
    }
    __syncthreads();
    if (s_frozen) return;

    bool act = tid < WW;
    int  s   = act ? tid : WW - 1;
    unsigned B0 = blockIdx.x * NB;
    unsigned c  = (B0 - (unsigned)HL + (unsigned)s) & MMSK;

    unsigned rl[6];
#pragma unroll
    for (int l = 0; l < 6; l++) rl[l] = (AINV * (c - (unsigned)l)) & MMSK;
    float2 llr = g_llr2[c];

    // load v2c row (3x LDG.128, coalesced) into own smem row
    const float4* gv = (const float4*)&g_v2c[rbuf][c * 6];
    float4 q0 = gv[0], q1 = gv[1], q2 = gv[2];
    if (act) {
        s_msg[s * ST + 0] = make_float2(q0.x, q0.y);
        s_msg[s * ST + 1] = make_float2(q0.z, q0.w);
        s_msg[s * ST + 2] = make_float2(q1.x, q1.y);
        s_msg[s * ST + 3] = make_float2(q1.z, q1.w);
        s_msg[s * ST + 4] = make_float2(q2.x, q2.y);
        s_msg[s * ST + 5] = make_float2(q2.z, q2.w);
    }
    if (tid < 5) {                                // zero beta pad rows
#pragma unroll
        for (int l = 0; l < 6; l++)
            s_beta[tid * ST + l] = make_float2(0.0f, 0.0f);
    }

    // beta rows for own base (contiguous 24B each, h=0 and h=1)
    const float* pr0 = betas + (size_t)t0 * EDG + rl[0] * 6u;
    const float* pr1 = pr0 + (size_t)MCC * 6u;
    float2 a0, a1, a2, b0, b1, b2;
    if (act) {
        a0 = *(const float2*)(pr0 + 0);
        a1 = *(const float2*)(pr0 + 2);
        a2 = *(const float2*)(pr0 + 4);
        b0 = *(const float2*)(pr1 + 0);
        b1 = *(const float2*)(pr1 + 2);
        b2 = *(const float2*)(pr1 + 4);
    }
    float2* gdst = g_v2c[rbuf ^ 1];

    for (int k = 1; k <= KK; k++) {
        // stage current betas; prefetch next iteration's rows
        if (act) {
            float2* br = &s_beta[(s + 5) * ST];
            br[0] = make_float2(a0.x, b0.x);
            br[1] = make_float2(a0.y, b0.y);
            br[2] = make_float2(a1.x, b1.x);
            br[3] = make_float2(a1.y, b1.y);
            br[4] = make_float2(a2.x, b2.x);
            br[5] = make_float2(a2.y, b2.y);
            if (k < KK) {
                pr0 += EDG; pr1 += EDG;
                a0 = *(const float2*)(pr0 + 0);
                a1 = *(const float2*)(pr0 + 2);
                a2 = *(const float2*)(pr0 + 4);
                b0 = *(const float2*)(pr1 + 0);
                b1 = *(const float2*)(pr1 + 2);
                b2 = *(const float2*)(pr1 + 4);
            }
        }
        __syncthreads();

        // ---- check phase: own row (12 edges in-thread) ----
        float2 v[6];
#pragma unroll
        for (int l = 0; l < 6; l++) v[l] = s_msg[s * ST + l];

        float m1 = __int_as_float(0x7f800000), m2 = m1;
        int   e1 = 0x7fffffff, tot = 0;
#pragma unroll
        for (int l = 0; l < 6; l++) {
            int eA = (int)(rl[l] * 6u + (unsigned)l);
            {   // h = 0
                float m = fabsf(v[l].x);
                tot += (v[l].x < 0.0f) ? 1 : 0;
                if (m < m1)       { m2 = m1; m1 = m; e1 = eA; }
                else if (m == m1) { m2 = m1; if (eA < e1) e1 = eA; }
                else if (m < m2)  { m2 = m; }
            }
            {   // h = 1
                int eB = eA + MC6;
                float m = fabsf(v[l].y);
                tot += (v[l].y < 0.0f) ? 1 : 0;
                if (m < m1)       { m2 = m1; m1 = m; e1 = eB; }
                else if (m == m1) { m2 = m1; if (eB < e1) e1 = eB; }
                else if (m < m2)  { m2 = m; }
            }
        }
#pragma unroll
        for (int l = 0; l < 6; l++) {
            float2 bb = s_beta[(s - l + 5) * ST + l];   // diag, conflict-free
            int eA = (int)(rl[l] * 6u + (unsigned)l);
            int nA = (v[l].x < 0.0f) ? 1 : 0;
            int nB = (v[l].y < 0.0f) ? 1 : 0;
            float sA = ((eA == e1) ? m2 : m1) * bb.x;
            float sB = ((eA + MC6 == e1) ? m2 : m1) * bb.y;
            float oA = ((tot - nA) & 1) ? -sA : sA;
            float oB = ((tot - nB) & 1) ? -sB : sB;
            if (act) s_msg[s * ST + l] = make_float2(oA, oB);  // c2v in place
        }
        __syncthreads();

        // ---- variable phase: diagonal (unique producer/consumer per elem) ----
        bool actv = tid < WW - 5;
        int  x    = actv ? tid : 0;
        float2 cv[6];
        float s0 = 0.0f, s1 = 0.0f;
#pragma unroll
        for (int l = 0; l < 6; l++) {
            cv[l] = s_msg[(x + l) * ST + l];
            s0 += cv[l].x; s1 += cv[l].y;
        }
        float tp0 = llr.x + s0;
        float tp1 = llr.y + s1;

        if (k < KK) {
            if (actv) {
#pragma unroll
                for (int l = 0; l < 6; l++)
                    s_msg[(x + l) * ST + l] =
                        make_float2(tp0 - cv[l].x, tp1 - cv[l].y);
            }
        } else if (tid >= HL && tid < HL + NB) {      // owned writeback
#pragma unroll
            for (int l = 0; l < 6; l++)
                gdst[(int)(((c + (unsigned)l) & MMSK) * 6u + (unsigned)l)] =
                    make_float2(tp0 - cv[l].x, tp1 - cv[l].y);
            g_post[c] = make_float2(tp0, tp1);
        }
        if (actv && tid >= HL - 5 && tid < HL + NB)
            sp[tid - (HL - 5)] =
                (unsigned char)(((tp0 < 0.0f) ? 1 : 0) ^ ((tp1 < 0.0f) ? 1 : 0));
        __syncthreads();

        int par = 0;
        if (tid < NB)
            par = sp[tid] ^ sp[tid + 1] ^ sp[tid + 2] ^ sp[tid + 3] ^
                  sp[tid + 4] ^ sp[tid + 5];
        int anyodd = __syncthreads_or(par);
        if (anyodd && tid == 0) g_synflag[t0 + k - 1] = 1;   // benign race
    }
}

// ---------------------------------------------------------------------------
__global__ void k_out(float* __restrict__ out, int out_size) {
    unsigned b = blockIdx.x * blockDim.x + threadIdx.x;   // base 0..MC-1
    float2 P = g_post[b];
    unsigned r = (AINV * b) & MMSK;

    if ((int)r < out_size)               out[r]             = (P.x < 0.0f) ? 1.0f : 0.0f;
    if ((int)(r + MCC) < out_size)       out[r + MCC]       = (P.y < 0.0f) ? 1.0f : 0.0f;
    if ((int)(NVV + r) < out_size)       out[NVV + r]       = P.x;
    if ((int)(NVV + r + MCC) < out_size) out[NVV + r + MCC] = P.y;

    if (b == 0 && 2 * NVV < out_size) {
        int iters = TMAXX;
        for (int tt = 0; tt < TMAXX; tt++)
            if (g_synflag[tt] == 0) { iters = tt + 1; break; }
        out[2 * NVV] = (float)iters;
    }
}

// ---------------------------------------------------------------------------
extern "C" void kernel_launch(void* const* d_in, const int* in_sizes, int n_in,
                              void* d_out, int out_size) {
    const float* llr   = (const float*)d_in[0];
    const float* betas = (const float*)d_in[1];
    (void)in_sizes; (void)n_in;

    k_init<<<MCC / 256, 256>>>(llr);
    for (int g = 0; g < NLAUNCH; g++)
        k_fused<<<GRD, THR>>>(betas, g * KK, g & 1);
    k_out<<<MCC / 256, 256>>>((float*)d_out, out_size);
}